// round 12
// baseline (speedup 1.0000x reference)
#include <cuda_runtime.h>
#include <cuda_bf16.h>
#include <cstdint>

// MinimalThinkingRefiner: out = x + alpha*(x*scale + shift) where mask[row]==2, else x.
// One CTA (512 threads) per TWO rows. Each thread handles chunk c of row0 and row1:
// two independent LDG.256 issued back-to-back (MLP=2) before the stores. No loop.

__device__ __forceinline__ void ldg_v8(const float4* p, float4& a, float4& b) {
    asm("ld.global.v8.b32 {%0,%1,%2,%3,%4,%5,%6,%7}, [%8];"
        : "=f"(a.x), "=f"(a.y), "=f"(a.z), "=f"(a.w),
          "=f"(b.x), "=f"(b.y), "=f"(b.z), "=f"(b.w)
        : "l"(p));
}

__device__ __forceinline__ void stg_v8(float4* p, const float4& a, const float4& b) {
    asm volatile("st.global.v8.b32 [%0], {%1,%2,%3,%4,%5,%6,%7,%8};"
        :: "l"(p),
           "f"(a.x), "f"(a.y), "f"(a.z), "f"(a.w),
           "f"(b.x), "f"(b.y), "f"(b.z), "f"(b.w)
        : "memory");
}

__device__ __forceinline__ void refine_pair(float4& a, float4& b,
                                            const float4& s0, const float4& s1,
                                            const float4& t0, const float4& t1,
                                            float al)
{
    a.x = fmaf(al, fmaf(a.x, s0.x, t0.x), a.x);
    a.y = fmaf(al, fmaf(a.y, s0.y, t0.y), a.y);
    a.z = fmaf(al, fmaf(a.z, s0.z, t0.z), a.z);
    a.w = fmaf(al, fmaf(a.w, s0.w, t0.w), a.w);
    b.x = fmaf(al, fmaf(b.x, s1.x, t1.x), b.x);
    b.y = fmaf(al, fmaf(b.y, s1.y, t1.y), b.y);
    b.z = fmaf(al, fmaf(b.z, s1.z, t1.z), b.z);
    b.w = fmaf(al, fmaf(b.w, s1.w, t1.w), b.w);
}

// Specialized: hv8 == 512. One CTA per 2 rows, 512 threads, one chunk/thread/row.
__global__ void __launch_bounds__(512, 4)
refiner_2row(const float4* __restrict__ x,
             const int*    __restrict__ mask,
             const float4* __restrict__ scale,
             const float4* __restrict__ shift,
             const float*  __restrict__ alpha_p,
             float4* __restrict__ out)
{
    const int row0 = blockIdx.x << 1;
    const int c    = threadIdx.x;                     // chunk index within each row
    // row stride in float4 units = 512 chunks * 2 = 1024
    const size_t b0 = ((size_t)row0 << 10) + ((size_t)c << 1);
    const size_t b1 = b0 + 1024;

    // Batch both independent 32-B loads before any dependent work (MLP=2).
    float4 a0, a1, d0, d1;
    ldg_v8(&x[b0], a0, a1);
    ldg_v8(&x[b1], d0, d1);

    const int m0 = mask[row0];
    const int m1 = mask[row0 + 1];

    if (m0 == 2 || m1 == 2) {
        const float al = __ldg(alpha_p);
        float4 s0, s1, t0, t1;
        ldg_v8(&scale[2 * c], s0, s1);
        ldg_v8(&shift[2 * c], t0, t1);
        if (m0 == 2) refine_pair(a0, a1, s0, s1, t0, t1, al);
        if (m1 == 2) refine_pair(d0, d1, s0, s1, t0, t1, al);
    }

    stg_v8(&out[b0], a0, a1);
    stg_v8(&out[b1], d0, d1);
}

// General fallback: loop over chunks, one CTA per row.
__global__ void __launch_bounds__(256, 8)
refiner_loop(const float4* __restrict__ x,
             const int*    __restrict__ mask,
             const float4* __restrict__ scale,
             const float4* __restrict__ shift,
             const float*  __restrict__ alpha_p,
             float4* __restrict__ out,
             int hv8)
{
    const int row = blockIdx.x;
    const bool thinking = (mask[row] == 2);
    const size_t base = (size_t)row * hv8 * 2;
    const float4* __restrict__ xr = x + base;
    float4* __restrict__ orow = out + base;
    const float al = thinking ? __ldg(alpha_p) : 0.0f;

    #pragma unroll 2
    for (int i = threadIdx.x; i < hv8; i += blockDim.x) {
        float4 a, b;
        ldg_v8(&xr[2 * i], a, b);
        if (thinking) {
            float4 s0, s1, t0, t1;
            ldg_v8(&scale[2 * i], s0, s1);
            ldg_v8(&shift[2 * i], t0, t1);
            refine_pair(a, b, s0, s1, t0, t1, al);
        }
        stg_v8(&orow[2 * i], a, b);
    }
}

extern "C" void kernel_launch(void* const* d_in, const int* in_sizes, int n_in,
                              void* d_out, int out_size)
{
    const float* x     = (const float*)d_in[0];   // [B,S,H]
    const int*   mask  = (const int*)d_in[1];     // [B,S]
    const float* scale = (const float*)d_in[2];   // [H]
    const float* shift = (const float*)d_in[3];   // [H]
    const float* alpha = (const float*)d_in[4];   // scalar

    const int rows = in_sizes[1];                 // B*S (16384)
    const int H    = in_sizes[0] / rows;          // 4096
    const int hv8  = H / 8;                       // 32-byte chunks per row (512)

    if (hv8 == 512 && (rows & 1) == 0) {
        refiner_2row<<<rows / 2, 512>>>(
            (const float4*)x, mask, (const float4*)scale, (const float4*)shift,
            alpha, (float4*)d_out);
    } else {
        refiner_loop<<<rows, 256>>>(
            (const float4*)x, mask, (const float4*)scale, (const float4*)shift,
            alpha, (float4*)d_out, hv8);
    }
}

// round 13
// speedup vs baseline: 1.0633x; 1.0633x over previous
#include <cuda_runtime.h>
#include <cuda_bf16.h>
#include <cstdint>

// MinimalThinkingRefiner: out = x + alpha*(x*scale + shift) where mask[row]==2, else x.
// FINAL: one CTA (512 threads) per row; each thread moves exactly one 32-byte chunk.
// Straight-line body (no loop). Mask broadcast load issued first so the predicate
// resolves under the x-load latency shadow. Measured optimum across 8 variants.

__device__ __forceinline__ void ldg_v8(const float4* p, float4& a, float4& b) {
    asm("ld.global.v8.b32 {%0,%1,%2,%3,%4,%5,%6,%7}, [%8];"
        : "=f"(a.x), "=f"(a.y), "=f"(a.z), "=f"(a.w),
          "=f"(b.x), "=f"(b.y), "=f"(b.z), "=f"(b.w)
        : "l"(p));
}

__device__ __forceinline__ void stg_v8(float4* p, const float4& a, const float4& b) {
    asm volatile("st.global.v8.b32 [%0], {%1,%2,%3,%4,%5,%6,%7,%8};"
        :: "l"(p),
           "f"(a.x), "f"(a.y), "f"(a.z), "f"(a.w),
           "f"(b.x), "f"(b.y), "f"(b.z), "f"(b.w)
        : "memory");
}

__device__ __forceinline__ void refine_chunk(float4& a, float4& b,
                                             const float4* scale, const float4* shift,
                                             int c, float al)
{
    float4 s0, s1, t0, t1;
    ldg_v8(&scale[2 * c], s0, s1);
    ldg_v8(&shift[2 * c], t0, t1);
    a.x = fmaf(al, fmaf(a.x, s0.x, t0.x), a.x);
    a.y = fmaf(al, fmaf(a.y, s0.y, t0.y), a.y);
    a.z = fmaf(al, fmaf(a.z, s0.z, t0.z), a.z);
    a.w = fmaf(al, fmaf(a.w, s0.w, t0.w), a.w);
    b.x = fmaf(al, fmaf(b.x, s1.x, t1.x), b.x);
    b.y = fmaf(al, fmaf(b.y, s1.y, t1.y), b.y);
    b.z = fmaf(al, fmaf(b.z, s1.z, t1.z), b.z);
    b.w = fmaf(al, fmaf(b.w, s1.w, t1.w), b.w);
}

// Specialized: blockDim.x == hv8 (one chunk per thread, no loop).
__global__ void __launch_bounds__(512, 4)
refiner_flat(const float4* __restrict__ x,
             const int*    __restrict__ mask,
             const float4* __restrict__ scale,
             const float4* __restrict__ shift,
             const float*  __restrict__ alpha_p,
             float4* __restrict__ out)
{
    const int row = blockIdx.x;
    const int c   = threadIdx.x;                       // chunk index in row
    const size_t base = ((size_t)row * blockDim.x + c) * 2;

    const int m = mask[row];                           // broadcast load, issued first
    float4 a, b;
    ldg_v8(&x[base], a, b);                            // predicate resolves under this
    if (m == 2) {
        refine_chunk(a, b, scale, shift, c, __ldg(alpha_p));
    }
    stg_v8(&out[base], a, b);
}

// General fallback: loop over chunks.
__global__ void __launch_bounds__(256, 8)
refiner_loop(const float4* __restrict__ x,
             const int*    __restrict__ mask,
             const float4* __restrict__ scale,
             const float4* __restrict__ shift,
             const float*  __restrict__ alpha_p,
             float4* __restrict__ out,
             int hv8)
{
    const int row = blockIdx.x;
    const bool thinking = (mask[row] == 2);
    const size_t base = (size_t)row * hv8 * 2;
    const float4* __restrict__ xr = x + base;
    float4* __restrict__ orow = out + base;
    const float al = thinking ? __ldg(alpha_p) : 0.0f;

    #pragma unroll 2
    for (int i = threadIdx.x; i < hv8; i += blockDim.x) {
        float4 a, b;
        ldg_v8(&xr[2 * i], a, b);
        if (thinking) refine_chunk(a, b, scale, shift, i, al);
        stg_v8(&orow[2 * i], a, b);
    }
}

extern "C" void kernel_launch(void* const* d_in, const int* in_sizes, int n_in,
                              void* d_out, int out_size)
{
    const float* x     = (const float*)d_in[0];   // [B,S,H]
    const int*   mask  = (const int*)d_in[1];     // [B,S]
    const float* scale = (const float*)d_in[2];   // [H]
    const float* shift = (const float*)d_in[3];   // [H]
    const float* alpha = (const float*)d_in[4];   // scalar

    const int rows = in_sizes[1];                 // B*S (16384)
    const int H    = in_sizes[0] / rows;          // 4096
    const int hv8  = H / 8;                       // 32-byte chunks per row (512)

    if (hv8 == 512) {
        refiner_flat<<<rows, 512>>>(
            (const float4*)x, mask, (const float4*)scale, (const float4*)shift,
            alpha, (float4*)d_out);
    } else {
        refiner_loop<<<rows, 256>>>(
            (const float4*)x, mask, (const float4*)scale, (const float4*)shift,
            alpha, (float4*)d_out, hv8);
    }
}

// round 15
// speedup vs baseline: 1.0810x; 1.0167x over previous
#include <cuda_runtime.h>
#include <cuda_bf16.h>
#include <cstdint>

// MinimalThinkingRefiner: out = x + alpha*(x*scale + shift) where mask[row]==2, else x.
// Probe: one CTA (1024 threads) per TWO rows, thread-split (lower 512 threads -> row0,
// upper 512 -> row1). Each thread: exactly one LDG.256 + one STG.256, per-row gating.
// Isolates CTA-count effect vs the R9 one-row flat optimum.

__device__ __forceinline__ void ldg_v8(const float4* p, float4& a, float4& b) {
    asm("ld.global.v8.b32 {%0,%1,%2,%3,%4,%5,%6,%7}, [%8];"
        : "=f"(a.x), "=f"(a.y), "=f"(a.z), "=f"(a.w),
          "=f"(b.x), "=f"(b.y), "=f"(b.z), "=f"(b.w)
        : "l"(p));
}

__device__ __forceinline__ void stg_v8(float4* p, const float4& a, const float4& b) {
    asm volatile("st.global.v8.b32 [%0], {%1,%2,%3,%4,%5,%6,%7,%8};"
        :: "l"(p),
           "f"(a.x), "f"(a.y), "f"(a.z), "f"(a.w),
           "f"(b.x), "f"(b.y), "f"(b.z), "f"(b.w)
        : "memory");
}

__device__ __forceinline__ void refine_chunk(float4& a, float4& b,
                                             const float4* scale, const float4* shift,
                                             int c, float al)
{
    float4 s0, s1, t0, t1;
    ldg_v8(&scale[2 * c], s0, s1);
    ldg_v8(&shift[2 * c], t0, t1);
    a.x = fmaf(al, fmaf(a.x, s0.x, t0.x), a.x);
    a.y = fmaf(al, fmaf(a.y, s0.y, t0.y), a.y);
    a.z = fmaf(al, fmaf(a.z, s0.z, t0.z), a.z);
    a.w = fmaf(al, fmaf(a.w, s0.w, t0.w), a.w);
    b.x = fmaf(al, fmaf(b.x, s1.x, t1.x), b.x);
    b.y = fmaf(al, fmaf(b.y, s1.y, t1.y), b.y);
    b.z = fmaf(al, fmaf(b.z, s1.z, t1.z), b.z);
    b.w = fmaf(al, fmaf(b.w, s1.w, t1.w), b.w);
}

// Probe: hv8 == 512, rows even. 1024 threads, thread-split over 2 rows.
__global__ void __launch_bounds__(1024, 2)
refiner_2row_split(const float4* __restrict__ x,
                   const int*    __restrict__ mask,
                   const float4* __restrict__ scale,
                   const float4* __restrict__ shift,
                   const float*  __restrict__ alpha_p,
                   float4* __restrict__ out)
{
    const int row = (blockIdx.x << 1) + (threadIdx.x >> 9);  // which of the 2 rows
    const int c   = threadIdx.x & 511;                       // chunk index in row
    const size_t base = ((size_t)row << 10) + ((size_t)c << 1);

    const int m = mask[row];                                 // per-half broadcast
    float4 a, b;
    ldg_v8(&x[base], a, b);
    if (m == 2) {
        refine_chunk(a, b, scale, shift, c, __ldg(alpha_p));
    }
    stg_v8(&out[base], a, b);
}

// Proven optimum (R9/R12): one CTA (512 threads) per row, one chunk per thread.
__global__ void __launch_bounds__(512, 4)
refiner_flat(const float4* __restrict__ x,
             const int*    __restrict__ mask,
             const float4* __restrict__ scale,
             const float4* __restrict__ shift,
             const float*  __restrict__ alpha_p,
             float4* __restrict__ out)
{
    const int row = blockIdx.x;
    const int c   = threadIdx.x;
    const size_t base = ((size_t)row * blockDim.x + c) * 2;

    const int m = mask[row];
    float4 a, b;
    ldg_v8(&x[base], a, b);
    if (m == 2) {
        refine_chunk(a, b, scale, shift, c, __ldg(alpha_p));
    }
    stg_v8(&out[base], a, b);
}

// General fallback: loop over chunks.
__global__ void __launch_bounds__(256, 8)
refiner_loop(const float4* __restrict__ x,
             const int*    __restrict__ mask,
             const float4* __restrict__ scale,
             const float4* __restrict__ shift,
             const float*  __restrict__ alpha_p,
             float4* __restrict__ out,
             int hv8)
{
    const int row = blockIdx.x;
    const bool thinking = (mask[row] == 2);
    const size_t base = (size_t)row * hv8 * 2;
    const float4* __restrict__ xr = x + base;
    float4* __restrict__ orow = out + base;
    const float al = thinking ? __ldg(alpha_p) : 0.0f;

    #pragma unroll 2
    for (int i = threadIdx.x; i < hv8; i += blockDim.x) {
        float4 a, b;
        ldg_v8(&xr[2 * i], a, b);
        if (thinking) refine_chunk(a, b, scale, shift, i, al);
        stg_v8(&orow[2 * i], a, b);
    }
}

extern "C" void kernel_launch(void* const* d_in, const int* in_sizes, int n_in,
                              void* d_out, int out_size)
{
    const float* x     = (const float*)d_in[0];   // [B,S,H]
    const int*   mask  = (const int*)d_in[1];     // [B,S]
    const float* scale = (const float*)d_in[2];   // [H]
    const float* shift = (const float*)d_in[3];   // [H]
    const float* alpha = (const float*)d_in[4];   // scalar

    const int rows = in_sizes[1];                 // B*S (16384)
    const int H    = in_sizes[0] / rows;          // 4096
    const int hv8  = H / 8;                       // 32-byte chunks per row (512)

    if (hv8 == 512 && (rows & 1) == 0) {
        refiner_2row_split<<<rows / 2, 1024>>>(
            (const float4*)x, mask, (const float4*)scale, (const float4*)shift,
            alpha, (float4*)d_out);
    } else if (hv8 == 512) {
        refiner_flat<<<rows, 512>>>(
            (const float4*)x, mask, (const float4*)scale, (const float4*)shift,
            alpha, (float4*)d_out);
    } else {
        refiner_loop<<<rows, 256>>>(
            (const float4*)x, mask, (const float4*)scale, (const float4*)shift,
            alpha, (float4*)d_out, hv8);
    }
}